// round 15
// baseline (speedup 1.0000x reference)
#include <cuda_runtime.h>
#include <cuda_fp16.h>
#include <math.h>
#include <stdint.h>

// Problem constants
#define B_   2
#define T_   2048
#define E_   2048
#define H_   16
#define HKV_ 4
#define D_   128
#define ROWS (B_ * T_)          // 4096
#define QCOLS (H_ * D_)         // 2048
#define KCOLS (HKV_ * D_)       // 512

// ---------------------------------------------------------------------------
// Scratch (allocation-free: device globals). All working tensors fp16.
// Weights transposed [N][K]. V stored TRANSPOSED: Vt[d'][token].
// ---------------------------------------------------------------------------
__device__ __align__(1024) __half g_xh [(size_t)ROWS * E_];
__device__ __align__(1024) __half g_WqT[(size_t)QCOLS * E_];
__device__ __align__(1024) __half g_WkT[(size_t)KCOLS * E_];
__device__ __align__(1024) __half g_WvT[(size_t)KCOLS * E_];
__device__ __align__(1024) __half g_WoT[(size_t)E_ * QCOLS];
__device__ __align__(1024) __half g_Q  [(size_t)ROWS * QCOLS];
__device__ __align__(1024) __half g_K  [(size_t)ROWS * KCOLS];
__device__ __align__(1024) __half g_Vt [(size_t)KCOLS * ROWS];   // [512][4096]
__device__ __align__(1024) __half g_ctx[(size_t)ROWS * QCOLS];
__device__ __align__(1024) float  g_rcos[T_ * 64];
__device__ __align__(1024) float  g_rsin[T_ * 64];

// ---------------------------------------------------------------------------
// Helpers
// ---------------------------------------------------------------------------
__device__ __forceinline__ uint32_t smem_u32(const void* p) {
    uint32_t a;
    asm("{ .reg .u64 t; cvta.to.shared.u64 t, %1; cvt.u32.u64 %0, t; }" : "=r"(a) : "l"(p));
    return a;
}
__device__ __forceinline__ void cp_async16(uint32_t saddr, const void* gptr) {
    asm volatile("cp.async.cg.shared.global [%0], [%1], 16;" :: "r"(saddr), "l"(gptr));
}
#define CP_COMMIT() asm volatile("cp.async.commit_group;" ::: "memory")
#define CP_WAIT(n)  asm volatile("cp.async.wait_group %0;" :: "n"(n) : "memory")

__device__ __forceinline__ uint32_t h2_bits(float a, float b) {
    __half2 h = __floats2half2_rn(a, b);
    return *(uint32_t*)&h;
}
__device__ __forceinline__ float2 h2_floats(uint32_t w) {
    __half2 h = *(__half2*)&w;
    return __half22float2(h);
}

// fp16 MMA: m16n8k16, fp32 accumulate.
__device__ __forceinline__ void mma_h(float* c, const uint32_t* a, const uint32_t* b) {
    asm volatile(
        "mma.sync.aligned.m16n8k16.row.col.f32.f16.f16.f32 "
        "{%0,%1,%2,%3}, {%4,%5,%6,%7}, {%8,%9}, {%0,%1,%2,%3};"
        : "+f"(c[0]), "+f"(c[1]), "+f"(c[2]), "+f"(c[3])
        : "r"(a[0]), "r"(a[1]), "r"(a[2]), "r"(a[3]), "r"(b[0]), "r"(b[1]));
}

// ---------------------------------------------------------------------------
// Rope cos/sin table (double-precision source, fp32 table).
// ---------------------------------------------------------------------------
__global__ void rope_table(float* __restrict__ ct, float* __restrict__ st) {
    int idx = blockIdx.x * blockDim.x + threadIdx.x;
    if (idx >= T_ * 64) return;
    int t = idx >> 6, i = idx & 63;
    double w = pow(10000.0, -(double)i / 64.0);
    double ds, dc;
    sincos((double)t * w, &ds, &dc);
    ct[idx] = (float)dc;
    st[idx] = (float)ds;
}

// ---------------------------------------------------------------------------
// Unified prep: blocks [0,10240) transpose+round the 4 weights (32x32 tiles),
// blocks [10240,14336) convert x fp32->fp16 (256 x uint4 per block).
// ---------------------------------------------------------------------------
__global__ void prep_all(const float* __restrict__ x,
                         const float* __restrict__ wq, const float* __restrict__ wk,
                         const float* __restrict__ wv, const float* __restrict__ wo,
                         __half* xh, __half* wqt, __half* wkt, __half* wvt, __half* wot) {
    int idx = blockIdx.x;
    int tid = threadIdx.x;
    if (idx >= 10240) {
        int i = (idx - 10240) * 256 + tid;
        const float4* in = (const float4*)x;
        float4 a = in[2 * i], b = in[2 * i + 1];
        uint4 o;
        o.x = h2_bits(a.x, a.y); o.y = h2_bits(a.z, a.w);
        o.z = h2_bits(b.x, b.y); o.w = h2_bits(b.z, b.w);
        ((uint4*)xh)[i] = o;
        return;
    }
    __shared__ float t[32][33];
    const float* in; __half* out; int K, N;
    if      (idx < 4096) { in = wq; out = wqt; K = E_;    N = QCOLS; }
    else if (idx < 5120) { in = wk; out = wkt; K = E_;    N = KCOLS; idx -= 4096; }
    else if (idx < 6144) { in = wv; out = wvt; K = E_;    N = KCOLS; idx -= 5120; }
    else                 { in = wo; out = wot; K = QCOLS; N = E_;    idx -= 6144; }
    int nb = N >> 5;
    int kb = idx / nb, jb = idx - kb * nb;
    int k0 = kb * 32, n0 = jb * 32;
    int tx = tid & 31, ty = tid >> 5;
    for (int i = ty; i < 32; i += 8)
        t[i][tx] = in[(size_t)(k0 + i) * N + n0 + tx];
    __syncthreads();
    for (int i = ty; i < 32; i += 8)
        out[(size_t)(n0 + i) * K + k0 + tx] = __float2half_rn(t[tx][i]);
}

// ---------------------------------------------------------------------------
// FP16 mma.sync GEMM (scalar fragment loads, 256 threads, 8 warps 2x4,
// warp tile 64x64, CTA 128x256, chunk K=64).
// 4-stage cp.async ring, prefetch depth 3, ONE barrier per chunk.
// 3-segment dispatch with per-segment A; segment 3 = Vt grid map.
// mode: 0 fp32 store, 1 fp16 store, 2 rope+scale (Q), 3 rope (K).
// ---------------------------------------------------------------------------
#define GBM 128
#define GBN 256
#define GBKH 64
#define GAST 36
#define GSTAGES 4
#define GA_W (GBM * GAST)       // 4608
#define GB_W (GBN * GAST)       // 9216
#define GSTAGE_W (GA_W + GB_W)  // 13824
#define GSMEM_BYTES (GSTAGES * GSTAGE_W * 4)   // 221184

__global__ __launch_bounds__(256, 1) void gemm_h(
    const __half* __restrict__ A1, const __half* __restrict__ B1,
    void* __restrict__ C1, int mode1, int nblk1, int N1,
    const __half* __restrict__ A2, const __half* __restrict__ B2,
    void* __restrict__ C2, int mode2, int nblk2, int N2,
    const __half* __restrict__ A3, const __half* __restrict__ B3,
    void* __restrict__ C3, int mode3, int N3,
    int K, const float* __restrict__ ct, const float* __restrict__ st)
{
    extern __shared__ __align__(16) uint32_t smw[];
    const int tid = threadIdx.x;
    const int wid = tid >> 5, lane = tid & 31;
    const int warpM = wid & 1, warpN = wid >> 1;   // 2 x 4, warp tile 64x64
    const int bx = blockIdx.x, by = blockIdx.y;

    const __half *A, *Bw; void* C; int mode, n0, N, m0;
    if (bx < nblk1) {
        A = A1; Bw = B1; C = C1; mode = mode1; N = N1;
        n0 = bx * GBN; m0 = by * GBM;
    } else if (bx < nblk1 + nblk2) {
        A = A2; Bw = B2; C = C2; mode = mode2; N = N2;
        n0 = (bx - nblk1) * GBN; m0 = by * GBM;
    } else {
        A = A3; Bw = B3; C = C3; mode = mode3; N = N3;
        m0 = (by & 3) * GBM;
        n0 = ((bx - nblk1 - nblk2) * 8 + (by >> 2)) * GBN;
    }

    const int nch = K / GBKH;
    const int lr = lane >> 2, lc = lane & 3;

    float acc[4][8][4];
#pragma unroll
    for (int i = 0; i < 4; i++)
#pragma unroll
        for (int j = 0; j < 8; j++)
#pragma unroll
            for (int q = 0; q < 4; q++) acc[i][j][q] = 0.f;

    const uint32_t smem_base = smem_u32(smw);

    auto load_chunk = [&](int c, int s) {
        uint32_t as_base = smem_base + s * GSTAGE_W * 4;
        uint32_t bs_base = as_base + GA_W * 4;
#pragma unroll
        for (int i = 0; i < 4; i++) {
            int ci = tid + i * 256;
            int row = ci >> 3, ch = ci & 7;
            cp_async16(as_base + (row * GAST + ch * 4) * 4,
                       A + (size_t)(m0 + row) * K + c * GBKH + ch * 8);
        }
#pragma unroll
        for (int i = 0; i < 8; i++) {
            int ci = tid + i * 256;
            int row = ci >> 3, ch = ci & 7;
            cp_async16(bs_base + (row * GAST + ch * 4) * 4,
                       Bw + (size_t)(n0 + row) * K + c * GBKH + ch * 8);
        }
    };

#pragma unroll
    for (int s = 0; s < GSTAGES - 1; s++) { load_chunk(s, s); CP_COMMIT(); }

    for (int c = 0; c < nch; c++) {
        // FIFO group completion: with >=2 newer groups outstanding, wait(2)
        // still guarantees chunk c has landed.
        int rem = nch - 1 - c;
        if (rem >= 2)      CP_WAIT(2);
        else if (rem == 1) CP_WAIT(1);
        else               CP_WAIT(0);
        __syncthreads();   // publish chunk c + fence last iter's readers

        int pc = c + GSTAGES - 1;
        if (pc < nch) { load_chunk(pc, pc & (GSTAGES - 1)); CP_COMMIT(); }

        const uint32_t* Asu = smw + (c & (GSTAGES - 1)) * GSTAGE_W;
        const uint32_t* Bsu = Asu + GA_W;

#pragma unroll
        for (int kk = 0; kk < 4; kk++) {       // 4 x k16 = 64 fp16
            uint32_t afr[4][4], bfr[8][2];
#pragma unroll
            for (int mt = 0; mt < 4; mt++) {
                int row = warpM * 64 + mt * 16 + lr;
                int col = kk * 8 + lc;
                afr[mt][0] = Asu[row * GAST + col];
                afr[mt][1] = Asu[(row + 8) * GAST + col];
                afr[mt][2] = Asu[row * GAST + col + 4];
                afr[mt][3] = Asu[(row + 8) * GAST + col + 4];
            }
#pragma unroll
            for (int nt = 0; nt < 8; nt++) {
                int n = warpN * 64 + nt * 8 + lr;
                int k = kk * 8 + lc;
                bfr[nt][0] = Bsu[n * GAST + k];
                bfr[nt][1] = Bsu[n * GAST + k + 4];
            }
#pragma unroll
            for (int mt = 0; mt < 4; mt++)
#pragma unroll
                for (int nt = 0; nt < 8; nt++)
                    mma_h(acc[mt][nt], afr[mt], bfr[nt]);
        }
    }

    // ---- fused epilogue ----
#pragma unroll
    for (int mt = 0; mt < 4; mt++) {
        int rbase = m0 + warpM * 64 + mt * 16 + lr;
#pragma unroll
        for (int nt = 0; nt < 8; nt++) {
            int cbase = n0 + warpN * 64 + nt * 8 + lc * 2;
            float4 v = make_float4(acc[mt][nt][0], acc[mt][nt][1],
                                   acc[mt][nt][2], acc[mt][nt][3]);
            if (mode >= 2) {
                int i  = (cbase & 127) >> 1;
                int t0 = rbase & (T_ - 1);
                int t1 = (rbase + 8) & (T_ - 1);
                float c0 = ct[(t0 << 6) + i], s0 = st[(t0 << 6) + i];
                float c1 = ct[(t1 << 6) + i], s1 = st[(t1 << 6) + i];
                float scale = (mode == 2) ? 0.08838834764831845f : 1.0f;
                float x0 = (v.x * c0 - v.y * s0) * scale;
                float y0 = (v.x * s0 + v.y * c0) * scale;
                float x1 = (v.z * c1 - v.w * s1) * scale;
                float y1 = (v.z * s1 + v.w * c1) * scale;
                v = make_float4(x0, y0, x1, y1);
            }
            if (mode == 0) {
                float* Cf = (float*)C;
                *(float2*)(Cf + (size_t)rbase * N + cbase)       = make_float2(v.x, v.y);
                *(float2*)(Cf + (size_t)(rbase + 8) * N + cbase) = make_float2(v.z, v.w);
            } else {
                __half* Ch = (__half*)C;
                *(uint32_t*)(Ch + (size_t)rbase * N + cbase)       = h2_bits(v.x, v.y);
                *(uint32_t*)(Ch + (size_t)(rbase + 8) * N + cbase) = h2_bits(v.z, v.w);
            }
        }
    }
}

// ---------------------------------------------------------------------------
// Causal flash attention, fp16 mma. FBM=128 (8 warps x 16 rows), BN=64 keys.
// 3-stage K/V ring, prefetch depth 2, ONE barrier per tile. P fp16 per warp,
// V from Vt (d-major).
// ---------------------------------------------------------------------------
#define FBM 128
#define KWST 68
#define VWST 36
#define PWST 68
#define FSTG 3
#define KS_W (FSTG * 64 * KWST)    // 13056
#define VS_W (FSTG * 128 * VWST)   // 13824
#define PS_W (8 * 16 * PWST)       // 8704
#define FA_SMEM_BYTES ((KS_W + VS_W + PS_W) * 4)   // 142336

__global__ __launch_bounds__(256, 1) void flash_h(const __half* __restrict__ Q,
                                                  const __half* __restrict__ Km,
                                                  const __half* __restrict__ Vt,
                                                  __half* __restrict__ ctx) {
    extern __shared__ __align__(16) uint32_t smw[];
    uint32_t* KsB = smw;
    uint32_t* VsB = smw + KS_W;
    uint32_t* PsB = VsB + VS_W;

    const int tid = threadIdx.x;
    const int wid = tid >> 5, lane = tid & 31;
    const int lr = lane >> 2, lc = lane & 3;
    const int m0 = (int)(gridDim.x - 1 - blockIdx.x) * FBM;   // heavy first
    const int h = blockIdx.y, b = blockIdx.z;
    const int kvh = h >> 2;

    uint32_t* Pw = PsB + wid * 16 * PWST;

    // ---- Q fragments (staged through P buffer) ----
    uint32_t qa[8][4];
    {
        const __half* qsrc = Q + (size_t)(b * T_ + m0 + wid * 16) * QCOLS + h * 128;
#pragma unroll
        for (int i = 0; i < 8; i++) {
            int task = lane + i * 32;           // 256 tasks: 16 rows x 16 chunks(8 fp16)
            int row = task >> 4, c4 = task & 15;
            uint4 v = *(const uint4*)(qsrc + (size_t)row * QCOLS + c4 * 8);
            *(uint4*)&Pw[row * PWST + c4 * 4] = v;
        }
        __syncwarp();
#pragma unroll
        for (int kk = 0; kk < 8; kk++) {
            qa[kk][0] = Pw[lr * PWST + kk * 8 + lc];
            qa[kk][1] = Pw[(lr + 8) * PWST + kk * 8 + lc];
            qa[kk][2] = Pw[lr * PWST + kk * 8 + lc + 4];
            qa[kk][3] = Pw[(lr + 8) * PWST + kk * 8 + lc + 4];
        }
        __syncwarp();
    }

    float oacc[16][4];
#pragma unroll
    for (int i = 0; i < 16; i++)
#pragma unroll
        for (int q = 0; q < 4; q++) oacc[i][q] = 0.f;
    float m_i[2] = {-1e30f, -1e30f};
    float l_i[2] = {0.f, 0.f};

    const int ntiles = m0 / 64 + 2;

    auto load_kv = [&](int t, int stg) {
        const __half* kb = Km + (size_t)(b * T_ + t * 64) * KCOLS + kvh * 128;
        const __half* vb = Vt + (size_t)(kvh * 128) * ROWS + b * T_ + t * 64;
        uint32_t ka = smem_u32(KsB + stg * 64 * KWST);
        uint32_t va = smem_u32(VsB + stg * 128 * VWST);
#pragma unroll
        for (int i = 0; i < 4; i++) {
            int task = tid + i * 256;
            int key = task >> 4, ch = task & 15;
            cp_async16(ka + (key * KWST + ch * 4) * 4, kb + (size_t)key * KCOLS + ch * 8);
        }
#pragma unroll
        for (int i = 0; i < 4; i++) {
            int task = tid + i * 256;
            int row = task >> 3, ch = task & 7;
            cp_async16(va + (row * VWST + ch * 4) * 4, vb + (size_t)row * ROWS + ch * 8);
        }
    };

    load_kv(0, 0);
    CP_COMMIT();
    if (ntiles > 1) { load_kv(1, 1); CP_COMMIT(); }

    for (int t = 0; t < ntiles; t++) {
        // FIFO completion: one newer group may stay outstanding.
        if (t + 1 < ntiles) CP_WAIT(1);
        else                CP_WAIT(0);
        __syncthreads();   // publish tile t + fence last iter's readers

        int pt = t + 2;
        if (pt < ntiles) { load_kv(pt, pt % FSTG); CP_COMMIT(); }

        const uint32_t* Kw = KsB + (t % FSTG) * 64 * KWST;
        const uint32_t* Vw = VsB + (t % FSTG) * 128 * VWST;

        // ---- S = Q K^T (8 k16 steps over D) ----
        float sacc[8][4];
#pragma unroll
        for (int nt = 0; nt < 8; nt++)
#pragma unroll
            for (int q = 0; q < 4; q++) sacc[nt][q] = 0.f;

#pragma unroll
        for (int kk = 0; kk < 8; kk++) {
            uint32_t bfr[8][2];
#pragma unroll
            for (int nt = 0; nt < 8; nt++) {
                bfr[nt][0] = Kw[(nt * 8 + lr) * KWST + kk * 8 + lc];
                bfr[nt][1] = Kw[(nt * 8 + lr) * KWST + kk * 8 + lc + 4];
            }
#pragma unroll
            for (int nt = 0; nt < 8; nt++)
                mma_h(sacc[nt], qa[kk], bfr[nt]);
        }

        // ---- causal mask ----
        const int row0g = m0 + wid * 16 + lr;
        const int row1g = row0g + 8;
        if (t * 64 + 63 > m0 + wid * 16) {
#pragma unroll
            for (int nt = 0; nt < 8; nt++) {
                int colg = t * 64 + nt * 8 + 2 * lc;
                if (colg     > row0g) sacc[nt][0] = -1e30f;
                if (colg + 1 > row0g) sacc[nt][1] = -1e30f;
                if (colg     > row1g) sacc[nt][2] = -1e30f;
                if (colg + 1 > row1g) sacc[nt][3] = -1e30f;
            }
        }

        // ---- online softmax ----
        float rmax0 = -1e30f, rmax1 = -1e30f;
#pragma unroll
        for (int nt = 0; nt < 8; nt++) {
            rmax0 = fmaxf(rmax0, fmaxf(sacc[nt][0], sacc[nt][1]));
            rmax1 = fmaxf(rmax1, fmaxf(sacc[nt][2], sacc[nt][3]));
        }
        rmax0 = fmaxf(rmax0, __shfl_xor_sync(0xffffffffu, rmax0, 1));
        rmax0 = fmaxf(rmax0, __shfl_xor_sync(0xffffffffu, rmax0, 2));
        rmax1 = fmaxf(rmax1, __shfl_xor_sync(0xffffffffu, rmax1, 1));
        rmax1 = fmaxf(rmax1, __shfl_xor_sync(0xffffffffu, rmax1, 2));

        float mnew0 = fmaxf(m_i[0], rmax0);
        float mnew1 = fmaxf(m_i[1], rmax1);
        float alpha0 = __expf(m_i[0] - mnew0);
        float alpha1 = __expf(m_i[1] - mnew1);

        float rsum0 = 0.f, rsum1 = 0.f;
#pragma unroll
        for (int nt = 0; nt < 8; nt++) {
            uint32_t w0 = h2_bits(__expf(sacc[nt][0] - mnew0), __expf(sacc[nt][1] - mnew0));
            uint32_t w1 = h2_bits(__expf(sacc[nt][2] - mnew1), __expf(sacc[nt][3] - mnew1));
            float2 p0 = h2_floats(w0);   // exact fp16 values fed to PV
            float2 p1 = h2_floats(w1);
            rsum0 += p0.x + p0.y;
            rsum1 += p1.x + p1.y;
            Pw[lr * PWST + nt * 4 + lc]       = w0;
            Pw[(lr + 8) * PWST + nt * 4 + lc] = w1;
        }
        rsum0 += __shfl_xor_sync(0xffffffffu, rsum0, 1);
        rsum0 += __shfl_xor_sync(0xffffffffu, rsum0, 2);
        rsum1 += __shfl_xor_sync(0xffffffffu, rsum1, 1);
        rsum1 += __shfl_xor_sync(0xffffffffu, rsum1, 2);

        l_i[0] = l_i[0] * alpha0 + rsum0;
        l_i[1] = l_i[1] * alpha1 + rsum1;
        m_i[0] = mnew0;
        m_i[1] = mnew1;
#pragma unroll
        for (int nt = 0; nt < 16; nt++) {
            oacc[nt][0] *= alpha0; oacc[nt][1] *= alpha0;
            oacc[nt][2] *= alpha1; oacc[nt][3] *= alpha1;
        }
        __syncwarp();

        // ---- O += P V  (4 k16 steps over 64 keys; V d-major) ----
#pragma unroll
        for (int kk = 0; kk < 4; kk++) {
            uint32_t pa[4];
            pa[0] = Pw[lr * PWST + kk * 8 + lc];
            pa[1] = Pw[(lr + 8) * PWST + kk * 8 + lc];
            pa[2] = Pw[lr * PWST + kk * 8 + lc + 4];
            pa[3] = Pw[(lr + 8) * PWST + kk * 8 + lc + 4];
#pragma unroll
            for (int nt = 0; nt < 16; nt++) {
                uint32_t bfr[2];
                bfr[0] = Vw[(nt * 8 + lr) * VWST + kk * 8 + lc];
                bfr[1] = Vw[(nt * 8 + lr) * VWST + kk * 8 + lc + 4];
                mma_h(oacc[nt], pa, bfr);
            }
        }
        __syncwarp();
    }

    // ---- epilogue: normalize, fp16 store ----
    float inv0 = 1.0f / l_i[0];
    float inv1 = 1.0f / l_i[1];
    const int row0g = m0 + wid * 16 + lr;
    __half* c0 = ctx + (size_t)(b * T_ + row0g) * QCOLS + h * 128;
    __half* c1 = ctx + (size_t)(b * T_ + row0g + 8) * QCOLS + h * 128;
#pragma unroll
    for (int nt = 0; nt < 16; nt++) {
        int col = nt * 8 + 2 * lc;
        *(uint32_t*)(c0 + col) = h2_bits(oacc[nt][0] * inv0, oacc[nt][1] * inv0);
        *(uint32_t*)(c1 + col) = h2_bits(oacc[nt][2] * inv1, oacc[nt][3] * inv1);
    }
}

// ---------------------------------------------------------------------------
// Host
// ---------------------------------------------------------------------------
extern "C" void kernel_launch(void* const* d_in, const int* in_sizes, int n_in,
                              void* d_out, int out_size) {
    const float* x    = (const float*)d_in[0];
    const float* Wq   = (const float*)d_in[1];
    const float* Wk   = (const float*)d_in[2];
    const float* Wv   = (const float*)d_in[3];
    const float* Wout = (const float*)d_in[4];
    float* out = (float*)d_out;

    __half *xh, *WqT, *WkT, *WvT, *WoT, *Qb, *Kb, *Vtb, *Cb;
    float *ctab, *stab;
    cudaGetSymbolAddress((void**)&xh,  g_xh);
    cudaGetSymbolAddress((void**)&WqT, g_WqT);
    cudaGetSymbolAddress((void**)&WkT, g_WkT);
    cudaGetSymbolAddress((void**)&WvT, g_WvT);
    cudaGetSymbolAddress((void**)&WoT, g_WoT);
    cudaGetSymbolAddress((void**)&Qb,  g_Q);
    cudaGetSymbolAddress((void**)&Kb,  g_K);
    cudaGetSymbolAddress((void**)&Vtb, g_Vt);
    cudaGetSymbolAddress((void**)&Cb,  g_ctx);
    cudaGetSymbolAddress((void**)&ctab, g_rcos);
    cudaGetSymbolAddress((void**)&stab, g_rsin);

    cudaFuncSetAttribute(gemm_h,  cudaFuncAttributeMaxDynamicSharedMemorySize, GSMEM_BYTES);
    cudaFuncSetAttribute(flash_h, cudaFuncAttributeMaxDynamicSharedMemorySize, FA_SMEM_BYTES);

    // 1) unified prep: weights transpose+round (10240 blocks) + x convert (4096)
    prep_all<<<14336, 256>>>(x, Wq, Wk, Wv, Wout, xh, WqT, WkT, WvT, WoT);

    // 2) rope table
    rope_table<<<(T_ * 64 + 255) / 256, 256>>>(ctab, stab);

    // 3) Q + K + V^T in ONE launch. grid (12, 32):
    //    bx 0..7  : Q  (A=xh, B=WqT, rope+scale, N=2048)
    //    bx 8..9  : K  (A=xh, B=WkT, rope,       N=512)
    //    bx 10..11: Vt (A=WvT, B=xh, fp16 store, N=4096)
    gemm_h<<<dim3(12, ROWS / GBM), 256, GSMEM_BYTES>>>(
        xh,  WqT, Qb,  2, QCOLS / GBN, QCOLS,
        xh,  WkT, Kb,  3, KCOLS / GBN, KCOLS,
        WvT, xh,  Vtb, 1, ROWS,
        E_, ctab, stab);

    // 4) attention (fp16 flash)
    flash_h<<<dim3(T_ / FBM, H_, B_), 256, FA_SMEM_BYTES>>>(Qb, Kb, Vtb, Cb);

    // 5) output projection: A = ctx fp16, C = out fp32. grid (8, 32), seg 1 only.
    gemm_h<<<dim3(E_ / GBN, ROWS / GBM), 256, GSMEM_BYTES>>>(
        Cb, WoT, out, 0, E_ / GBN, E_,
        Cb, WoT, out, 0, 0, E_,
        Cb, WoT, out, 0, E_,
        QCOLS, ctab, stab);
}

// round 16
// speedup vs baseline: 1.0488x; 1.0488x over previous
#include <cuda_runtime.h>
#include <cuda_fp16.h>
#include <math.h>
#include <stdint.h>

// Problem constants
#define B_   2
#define T_   2048
#define E_   2048
#define H_   16
#define HKV_ 4
#define D_   128
#define ROWS (B_ * T_)          // 4096
#define QCOLS (H_ * D_)         // 2048
#define KCOLS (HKV_ * D_)       // 512

// ---------------------------------------------------------------------------
// Scratch (allocation-free: device globals). All working tensors fp16.
// Weights transposed [N][K]. V stored TRANSPOSED: Vt[d'][token].
// ---------------------------------------------------------------------------
__device__ __align__(1024) __half g_xh [(size_t)ROWS * E_];
__device__ __align__(1024) __half g_WqT[(size_t)QCOLS * E_];
__device__ __align__(1024) __half g_WkT[(size_t)KCOLS * E_];
__device__ __align__(1024) __half g_WvT[(size_t)KCOLS * E_];
__device__ __align__(1024) __half g_WoT[(size_t)E_ * QCOLS];
__device__ __align__(1024) __half g_Q  [(size_t)ROWS * QCOLS];
__device__ __align__(1024) __half g_K  [(size_t)ROWS * KCOLS];
__device__ __align__(1024) __half g_Vt [(size_t)KCOLS * ROWS];   // [512][4096]
__device__ __align__(1024) __half g_ctx[(size_t)ROWS * QCOLS];
__device__ __align__(1024) float  g_rcos[T_ * 64];
__device__ __align__(1024) float  g_rsin[T_ * 64];

// ---------------------------------------------------------------------------
// Helpers
// ---------------------------------------------------------------------------
__device__ __forceinline__ uint32_t smem_u32(const void* p) {
    uint32_t a;
    asm("{ .reg .u64 t; cvta.to.shared.u64 t, %1; cvt.u32.u64 %0, t; }" : "=r"(a) : "l"(p));
    return a;
}
__device__ __forceinline__ void cp_async16(uint32_t saddr, const void* gptr) {
    asm volatile("cp.async.cg.shared.global [%0], [%1], 16;" :: "r"(saddr), "l"(gptr));
}
#define CP_COMMIT() asm volatile("cp.async.commit_group;" ::: "memory")
#define CP_WAIT(n)  asm volatile("cp.async.wait_group %0;" :: "n"(n) : "memory")

__device__ __forceinline__ uint32_t h2_bits(float a, float b) {
    __half2 h = __floats2half2_rn(a, b);
    return *(uint32_t*)&h;
}
__device__ __forceinline__ float2 h2_floats(uint32_t w) {
    __half2 h = *(__half2*)&w;
    return __half22float2(h);
}

// fp16 MMA: m16n8k16, fp32 accumulate.
__device__ __forceinline__ void mma_h(float* c, const uint32_t* a, const uint32_t* b) {
    asm volatile(
        "mma.sync.aligned.m16n8k16.row.col.f32.f16.f16.f32 "
        "{%0,%1,%2,%3}, {%4,%5,%6,%7}, {%8,%9}, {%0,%1,%2,%3};"
        : "+f"(c[0]), "+f"(c[1]), "+f"(c[2]), "+f"(c[3])
        : "r"(a[0]), "r"(a[1]), "r"(a[2]), "r"(a[3]), "r"(b[0]), "r"(b[1]));
}

// ---------------------------------------------------------------------------
// Unified prep:
//   blocks [0,10240)      : weight transpose + fp16 round (32x32 tiles)
//   blocks [10240,14336)  : x fp32 -> fp16 (256 x uint4 per block)
//   blocks [14336,14848)  : rope cos/sin table (double-precision source)
// ---------------------------------------------------------------------------
__global__ void prep_all(const float* __restrict__ x,
                         const float* __restrict__ wq, const float* __restrict__ wk,
                         const float* __restrict__ wv, const float* __restrict__ wo,
                         __half* xh, __half* wqt, __half* wkt, __half* wvt, __half* wot,
                         float* __restrict__ ct, float* __restrict__ st) {
    int idx = blockIdx.x;
    int tid = threadIdx.x;
    if (idx >= 14336) {
        int e = (idx - 14336) * 256 + tid;      // 131072 entries
        int t = e >> 6, i = e & 63;
        double w = pow(10000.0, -(double)i / 64.0);
        double ds, dc;
        sincos((double)t * w, &ds, &dc);
        ct[e] = (float)dc;
        st[e] = (float)ds;
        return;
    }
    if (idx >= 10240) {
        int i = (idx - 10240) * 256 + tid;
        const float4* in = (const float4*)x;
        float4 a = in[2 * i], b = in[2 * i + 1];
        uint4 o;
        o.x = h2_bits(a.x, a.y); o.y = h2_bits(a.z, a.w);
        o.z = h2_bits(b.x, b.y); o.w = h2_bits(b.z, b.w);
        ((uint4*)xh)[i] = o;
        return;
    }
    __shared__ float t[32][33];
    const float* in; __half* out; int K, N;
    if      (idx < 4096) { in = wq; out = wqt; K = E_;    N = QCOLS; }
    else if (idx < 5120) { in = wk; out = wkt; K = E_;    N = KCOLS; idx -= 4096; }
    else if (idx < 6144) { in = wv; out = wvt; K = E_;    N = KCOLS; idx -= 5120; }
    else                 { in = wo; out = wot; K = QCOLS; N = E_;    idx -= 6144; }
    int nb = N >> 5;
    int kb = idx / nb, jb = idx - kb * nb;
    int k0 = kb * 32, n0 = jb * 32;
    int tx = tid & 31, ty = tid >> 5;
    for (int i = ty; i < 32; i += 8)
        t[i][tx] = in[(size_t)(k0 + i) * N + n0 + tx];
    __syncthreads();
    for (int i = ty; i < 32; i += 8)
        out[(size_t)(n0 + i) * K + k0 + tx] = __float2half_rn(t[tx][i]);
}

// ---------------------------------------------------------------------------
// FP16 mma.sync GEMM (R14 config: scalar fragment loads, 256 threads,
// 8 warps 2x4, warp tile 64x64, CTA 128x256, chunk K=64, 3-stage cp.async,
// single barrier per chunk). 3-segment dispatch; segment 3 = Vt grid map.
// mode: 0 fp32 store, 1 fp16 store, 2 rope+scale (Q, scale incl. log2e),
// 3 rope (K).
// ---------------------------------------------------------------------------
#define GBM 128
#define GBN 256
#define GBKH 64
#define GAST 36
#define GSTAGES 3
#define GA_W (GBM * GAST)       // 4608
#define GB_W (GBN * GAST)       // 9216
#define GSTAGE_W (GA_W + GB_W)  // 13824
#define GSMEM_BYTES (GSTAGES * GSTAGE_W * 4)   // 165888

// 1/sqrt(128) * log2(e): S computed in log2 domain for exp2-softmax.
#define QSCALE (0.08838834764831845f * 1.4426950408889634f)

__global__ __launch_bounds__(256, 1) void gemm_h(
    const __half* __restrict__ A1, const __half* __restrict__ B1,
    void* __restrict__ C1, int mode1, int nblk1, int N1,
    const __half* __restrict__ A2, const __half* __restrict__ B2,
    void* __restrict__ C2, int mode2, int nblk2, int N2,
    const __half* __restrict__ A3, const __half* __restrict__ B3,
    void* __restrict__ C3, int mode3, int N3,
    int K, const float* __restrict__ ct, const float* __restrict__ st)
{
    extern __shared__ __align__(16) uint32_t smw[];
    const int tid = threadIdx.x;
    const int wid = tid >> 5, lane = tid & 31;
    const int warpM = wid & 1, warpN = wid >> 1;   // 2 x 4, warp tile 64x64
    const int bx = blockIdx.x, by = blockIdx.y;

    const __half *A, *Bw; void* C; int mode, n0, N, m0;
    if (bx < nblk1) {
        A = A1; Bw = B1; C = C1; mode = mode1; N = N1;
        n0 = bx * GBN; m0 = by * GBM;
    } else if (bx < nblk1 + nblk2) {
        A = A2; Bw = B2; C = C2; mode = mode2; N = N2;
        n0 = (bx - nblk1) * GBN; m0 = by * GBM;
    } else {
        A = A3; Bw = B3; C = C3; mode = mode3; N = N3;
        m0 = (by & 3) * GBM;
        n0 = ((bx - nblk1 - nblk2) * 8 + (by >> 2)) * GBN;
    }

    const int nch = K / GBKH;
    const int lr = lane >> 2, lc = lane & 3;

    float acc[4][8][4];
#pragma unroll
    for (int i = 0; i < 4; i++)
#pragma unroll
        for (int j = 0; j < 8; j++)
#pragma unroll
            for (int q = 0; q < 4; q++) acc[i][j][q] = 0.f;

    const uint32_t smem_base = smem_u32(smw);

    auto load_chunk = [&](int c, int s) {
        uint32_t as_base = smem_base + s * GSTAGE_W * 4;
        uint32_t bs_base = as_base + GA_W * 4;
#pragma unroll
        for (int i = 0; i < 4; i++) {
            int ci = tid + i * 256;
            int row = ci >> 3, ch = ci & 7;
            cp_async16(as_base + (row * GAST + ch * 4) * 4,
                       A + (size_t)(m0 + row) * K + c * GBKH + ch * 8);
        }
#pragma unroll
        for (int i = 0; i < 8; i++) {
            int ci = tid + i * 256;
            int row = ci >> 3, ch = ci & 7;
            cp_async16(bs_base + (row * GAST + ch * 4) * 4,
                       Bw + (size_t)(n0 + row) * K + c * GBKH + ch * 8);
        }
    };

#pragma unroll
    for (int s = 0; s < GSTAGES - 1; s++) { load_chunk(s, s); CP_COMMIT(); }

    for (int c = 0; c < nch; c++) {
        CP_WAIT(GSTAGES - 2);
        __syncthreads();

        int pc = c + GSTAGES - 1;
        if (pc < nch) { load_chunk(pc, pc % GSTAGES); CP_COMMIT(); }

        const uint32_t* Asu = smw + (c % GSTAGES) * GSTAGE_W;
        const uint32_t* Bsu = Asu + GA_W;

#pragma unroll
        for (int kk = 0; kk < 4; kk++) {       // 4 x k16 = 64 fp16
            uint32_t afr[4][4], bfr[8][2];
#pragma unroll
            for (int mt = 0; mt < 4; mt++) {
                int row = warpM * 64 + mt * 16 + lr;
                int col = kk * 8 + lc;
                afr[mt][0] = Asu[row * GAST + col];
                afr[mt][1] = Asu[(row + 8) * GAST + col];
                afr[mt][2] = Asu[row * GAST + col + 4];
                afr[mt][3] = Asu[(row + 8) * GAST + col + 4];
            }
#pragma unroll
            for (int nt = 0; nt < 8; nt++) {
                int n = warpN * 64 + nt * 8 + lr;
                int k = kk * 8 + lc;
                bfr[nt][0] = Bsu[n * GAST + k];
                bfr[nt][1] = Bsu[n * GAST + k + 4];
            }
#pragma unroll
            for (int mt = 0; mt < 4; mt++)
#pragma unroll
                for (int nt = 0; nt < 8; nt++)
                    mma_h(acc[mt][nt], afr[mt], bfr[nt]);
        }
    }

    // ---- fused epilogue ----
#pragma unroll
    for (int mt = 0; mt < 4; mt++) {
        int rbase = m0 + warpM * 64 + mt * 16 + lr;
#pragma unroll
        for (int nt = 0; nt < 8; nt++) {
            int cbase = n0 + warpN * 64 + nt * 8 + lc * 2;
            float4 v = make_float4(acc[mt][nt][0], acc[mt][nt][1],
                                   acc[mt][nt][2], acc[mt][nt][3]);
            if (mode >= 2) {
                int i  = (cbase & 127) >> 1;
                int t0 = rbase & (T_ - 1);
                int t1 = (rbase + 8) & (T_ - 1);
                float c0 = ct[(t0 << 6) + i], s0 = st[(t0 << 6) + i];
                float c1 = ct[(t1 << 6) + i], s1 = st[(t1 << 6) + i];
                float scale = (mode == 2) ? QSCALE : 1.0f;
                float x0 = (v.x * c0 - v.y * s0) * scale;
                float y0 = (v.x * s0 + v.y * c0) * scale;
                float x1 = (v.z * c1 - v.w * s1) * scale;
                float y1 = (v.z * s1 + v.w * c1) * scale;
                v = make_float4(x0, y0, x1, y1);
            }
            if (mode == 0) {
                float* Cf = (float*)C;
                *(float2*)(Cf + (size_t)rbase * N + cbase)       = make_float2(v.x, v.y);
                *(float2*)(Cf + (size_t)(rbase + 8) * N + cbase) = make_float2(v.z, v.w);
            } else {
                __half* Ch = (__half*)C;
                *(uint32_t*)(Ch + (size_t)rbase * N + cbase)       = h2_bits(v.x, v.y);
                *(uint32_t*)(Ch + (size_t)(rbase + 8) * N + cbase) = h2_bits(v.z, v.w);
            }
        }
    }
}

// ---------------------------------------------------------------------------
// Causal flash attention, fp16 mma, REGISTER-RESIDENT P, exp2 softmax.
// FBM=128 (8 warps x 16 rows), BN=64 keys. K/V double-buffered.
// P fragments built directly from S fragment registers (C-layout of two
// adjacent 8-col tiles == A-layout of one k16 chunk). V from Vt (d-major).
// ---------------------------------------------------------------------------
#define FBM 128
#define KWST 68
#define VWST 36
#define PWST 68
#define KS_W (2 * 64 * KWST)    // 8704
#define VS_W (2 * 128 * VWST)   // 9216
#define PS_W (8 * 16 * PWST)    // 8704 (Q staging only)
#define FA_SMEM_BYTES ((KS_W + VS_W + PS_W) * 4)   // 106496

__global__ __launch_bounds__(256, 1) void flash_h(const __half* __restrict__ Q,
                                                  const __half* __restrict__ Km,
                                                  const __half* __restrict__ Vt,
                                                  __half* __restrict__ ctx) {
    extern __shared__ __align__(16) uint32_t smw[];
    uint32_t* KsB = smw;
    uint32_t* VsB = smw + KS_W;
    uint32_t* PsB = VsB + VS_W;

    const int tid = threadIdx.x;
    const int wid = tid >> 5, lane = tid & 31;
    const int lr = lane >> 2, lc = lane & 3;
    const int m0 = (int)(gridDim.x - 1 - blockIdx.x) * FBM;   // heavy first
    const int h = blockIdx.y, b = blockIdx.z;
    const int kvh = h >> 2;

    uint32_t* Pw = PsB + wid * 16 * PWST;

    // ---- Q fragments (staged through per-warp buffer) ----
    uint32_t qa[8][4];
    {
        const __half* qsrc = Q + (size_t)(b * T_ + m0 + wid * 16) * QCOLS + h * 128;
#pragma unroll
        for (int i = 0; i < 8; i++) {
            int task = lane + i * 32;           // 256 tasks: 16 rows x 16 chunks(8 fp16)
            int row = task >> 4, c4 = task & 15;
            uint4 v = *(const uint4*)(qsrc + (size_t)row * QCOLS + c4 * 8);
            *(uint4*)&Pw[row * PWST + c4 * 4] = v;
        }
        __syncwarp();
#pragma unroll
        for (int kk = 0; kk < 8; kk++) {
            qa[kk][0] = Pw[lr * PWST + kk * 8 + lc];
            qa[kk][1] = Pw[(lr + 8) * PWST + kk * 8 + lc];
            qa[kk][2] = Pw[lr * PWST + kk * 8 + lc + 4];
            qa[kk][3] = Pw[(lr + 8) * PWST + kk * 8 + lc + 4];
        }
        __syncwarp();
    }

    float oacc[16][4];
#pragma unroll
    for (int i = 0; i < 16; i++)
#pragma unroll
        for (int q = 0; q < 4; q++) oacc[i][q] = 0.f;
    float m_i[2] = {-1e30f, -1e30f};   // log2 domain
    float l_i[2] = {0.f, 0.f};

    const int ntiles = m0 / 64 + 2;

    auto load_kv = [&](int t, int stg) {
        const __half* kb = Km + (size_t)(b * T_ + t * 64) * KCOLS + kvh * 128;
        const __half* vb = Vt + (size_t)(kvh * 128) * ROWS + b * T_ + t * 64;
        uint32_t ka = smem_u32(KsB + stg * 64 * KWST);
        uint32_t va = smem_u32(VsB + stg * 128 * VWST);
#pragma unroll
        for (int i = 0; i < 4; i++) {
            int task = tid + i * 256;
            int key = task >> 4, ch = task & 15;
            cp_async16(ka + (key * KWST + ch * 4) * 4, kb + (size_t)key * KCOLS + ch * 8);
        }
#pragma unroll
        for (int i = 0; i < 4; i++) {
            int task = tid + i * 256;
            int row = task >> 3, ch = task & 7;
            cp_async16(va + (row * VWST + ch * 4) * 4, vb + (size_t)row * ROWS + ch * 8);
        }
    };

    load_kv(0, 0);
    CP_COMMIT();

    for (int t = 0; t < ntiles; t++) {
        if (t + 1 < ntiles) { load_kv(t + 1, (t + 1) & 1); CP_COMMIT(); CP_WAIT(1); }
        else                { CP_WAIT(0); }
        __syncthreads();

        const uint32_t* Kw = KsB + (t & 1) * 64 * KWST;
        const uint32_t* Vw = VsB + (t & 1) * 128 * VWST;

        // ---- S = Q K^T (8 k16 steps over D); S in log2 units ----
        float sacc[8][4];
#pragma unroll
        for (int nt = 0; nt < 8; nt++)
#pragma unroll
            for (int q = 0; q < 4; q++) sacc[nt][q] = 0.f;

#pragma unroll
        for (int kk = 0; kk < 8; kk++) {
            uint32_t bfr[8][2];
#pragma unroll
            for (int nt = 0; nt < 8; nt++) {
                bfr[nt][0] = Kw[(nt * 8 + lr) * KWST + kk * 8 + lc];
                bfr[nt][1] = Kw[(nt * 8 + lr) * KWST + kk * 8 + lc + 4];
            }
#pragma unroll
            for (int nt = 0; nt < 8; nt++)
                mma_h(sacc[nt], qa[kk], bfr[nt]);
        }

        // ---- causal mask ----
        const int row0g = m0 + wid * 16 + lr;
        const int row1g = row0g + 8;
        if (t * 64 + 63 > m0 + wid * 16) {
#pragma unroll
            for (int nt = 0; nt < 8; nt++) {
                int colg = t * 64 + nt * 8 + 2 * lc;
                if (colg     > row0g) sacc[nt][0] = -1e30f;
                if (colg + 1 > row0g) sacc[nt][1] = -1e30f;
                if (colg     > row1g) sacc[nt][2] = -1e30f;
                if (colg + 1 > row1g) sacc[nt][3] = -1e30f;
            }
        }

        // ---- online softmax (exp2 domain) ----
        float rmax0 = -1e30f, rmax1 = -1e30f;
#pragma unroll
        for (int nt = 0; nt < 8; nt++) {
            rmax0 = fmaxf(rmax0, fmaxf(sacc[nt][0], sacc[nt][1]));
            rmax1 = fmaxf(rmax1, fmaxf(sacc[nt][2], sacc[nt][3]));
        }
        rmax0 = fmaxf(rmax0, __shfl_xor_sync(0xffffffffu, rmax0, 1));
        rmax0 = fmaxf(rmax0, __shfl_xor_sync(0xffffffffu, rmax0, 2));
        rmax1 = fmaxf(rmax1, __shfl_xor_sync(0xffffffffu, rmax1, 1));
        rmax1 = fmaxf(rmax1, __shfl_xor_sync(0xffffffffu, rmax1, 2));

        float mnew0 = fmaxf(m_i[0], rmax0);
        float mnew1 = fmaxf(m_i[1], rmax1);
        float alpha0 = exp2f(m_i[0] - mnew0);
        float alpha1 = exp2f(m_i[1] - mnew1);

        // P fragments directly in registers (no smem round-trip).
        uint32_t pw0[8], pw1[8];
        float rsum0 = 0.f, rsum1 = 0.f;
#pragma unroll
        for (int nt = 0; nt < 8; nt++) {
            uint32_t w0 = h2_bits(exp2f(sacc[nt][0] - mnew0), exp2f(sacc[nt][1] - mnew0));
            uint32_t w1 = h2_bits(exp2f(sacc[nt][2] - mnew1), exp2f(sacc[nt][3] - mnew1));
            float2 p0 = h2_floats(w0);   // exact fp16 values fed to PV
            float2 p1 = h2_floats(w1);
            rsum0 += p0.x + p0.y;
            rsum1 += p1.x + p1.y;
            pw0[nt] = w0;
            pw1[nt] = w1;
        }
        rsum0 += __shfl_xor_sync(0xffffffffu, rsum0, 1);
        rsum0 += __shfl_xor_sync(0xffffffffu, rsum0, 2);
        rsum1 += __shfl_xor_sync(0xffffffffu, rsum1, 1);
        rsum1 += __shfl_xor_sync(0xffffffffu, rsum1, 2);

        l_i[0] = l_i[0] * alpha0 + rsum0;
        l_i[1] = l_i[1] * alpha1 + rsum1;
        m_i[0] = mnew0;
        m_i[1] = mnew1;
#pragma unroll
        for (int nt = 0; nt < 16; nt++) {
            oacc[nt][0] *= alpha0; oacc[nt][1] *= alpha0;
            oacc[nt][2] *= alpha1; oacc[nt][3] *= alpha1;
        }

        // ---- O += P V  (4 k16 steps over 64 keys; pa from registers) ----
#pragma unroll
        for (int kk = 0; kk < 4; kk++) {
            uint32_t pa[4];
            pa[0] = pw0[2 * kk];
            pa[1] = pw1[2 * kk];
            pa[2] = pw0[2 * kk + 1];
            pa[3] = pw1[2 * kk + 1];
#pragma unroll
            for (int nt = 0; nt < 16; nt++) {
                uint32_t bfr[2];
                bfr[0] = Vw[(nt * 8 + lr) * VWST + kk * 8 + lc];
                bfr[1] = Vw[(nt * 8 + lr) * VWST + kk * 8 + lc + 4];
                mma_h(oacc[nt], pa, bfr);
            }
        }
        __syncthreads();   // all warps done with stage (t&1) before overwrite
    }

    // ---- epilogue: normalize, fp16 store ----
    float inv0 = 1.0f / l_i[0];
    float inv1 = 1.0f / l_i[1];
    const int row0g = m0 + wid * 16 + lr;
    __half* c0 = ctx + (size_t)(b * T_ + row0g) * QCOLS + h * 128;
    __half* c1 = ctx + (size_t)(b * T_ + row0g + 8) * QCOLS + h * 128;
#pragma unroll
    for (int nt = 0; nt < 16; nt++) {
        int col = nt * 8 + 2 * lc;
        *(uint32_t*)(c0 + col) = h2_bits(oacc[nt][0] * inv0, oacc[nt][1] * inv0);
        *(uint32_t*)(c1 + col) = h2_bits(oacc[nt][2] * inv1, oacc[nt][3] * inv1);
    }
}

// ---------------------------------------------------------------------------
// Host
// ---------------------------------------------------------------------------
extern "C" void kernel_launch(void* const* d_in, const int* in_sizes, int n_in,
                              void* d_out, int out_size) {
    const float* x    = (const float*)d_in[0];
    const float* Wq   = (const float*)d_in[1];
    const float* Wk   = (const float*)d_in[2];
    const float* Wv   = (const float*)d_in[3];
    const float* Wout = (const float*)d_in[4];
    float* out = (float*)d_out;

    __half *xh, *WqT, *WkT, *WvT, *WoT, *Qb, *Kb, *Vtb, *Cb;
    float *ctab, *stab;
    cudaGetSymbolAddress((void**)&xh,  g_xh);
    cudaGetSymbolAddress((void**)&WqT, g_WqT);
    cudaGetSymbolAddress((void**)&WkT, g_WkT);
    cudaGetSymbolAddress((void**)&WvT, g_WvT);
    cudaGetSymbolAddress((void**)&WoT, g_WoT);
    cudaGetSymbolAddress((void**)&Qb,  g_Q);
    cudaGetSymbolAddress((void**)&Kb,  g_K);
    cudaGetSymbolAddress((void**)&Vtb, g_Vt);
    cudaGetSymbolAddress((void**)&Cb,  g_ctx);
    cudaGetSymbolAddress((void**)&ctab, g_rcos);
    cudaGetSymbolAddress((void**)&stab, g_rsin);

    cudaFuncSetAttribute(gemm_h,  cudaFuncAttributeMaxDynamicSharedMemorySize, GSMEM_BYTES);
    cudaFuncSetAttribute(flash_h, cudaFuncAttributeMaxDynamicSharedMemorySize, FA_SMEM_BYTES);

    // 1) unified prep: weights (10240) + x convert (4096) + rope table (512)
    prep_all<<<14848, 256>>>(x, Wq, Wk, Wv, Wout, xh, WqT, WkT, WvT, WoT, ctab, stab);

    // 2) Q + K + V^T in ONE launch. grid (12, 32):
    //    bx 0..7  : Q  (A=xh, B=WqT, rope + 1/sqrt(D)*log2e, N=2048)
    //    bx 8..9  : K  (A=xh, B=WkT, rope,                   N=512)
    //    bx 10..11: Vt (A=WvT, B=xh, fp16 store,             N=4096)
    gemm_h<<<dim3(12, ROWS / GBM), 256, GSMEM_BYTES>>>(
        xh,  WqT, Qb,  2, QCOLS / GBN, QCOLS,
        xh,  WkT, Kb,  3, KCOLS / GBN, KCOLS,
        WvT, xh,  Vtb, 1, ROWS,
        E_, ctab, stab);

    // 3) attention (fp16 flash, register-P, exp2 softmax)
    flash_h<<<dim3(T_ / FBM, H_, B_), 256, FA_SMEM_BYTES>>>(Qb, Kb, Vtb, Cb);

    // 4) output projection: A = ctx fp16, C = out fp32. grid (8, 32), seg 1 only.
    gemm_h<<<dim3(E_ / GBN, ROWS / GBM), 256, GSMEM_BYTES>>>(
        Cb, WoT, out, 0, E_ / GBN, E_,
        Cb, WoT, out, 0, 0, E_,
        Cb, WoT, out, 0, E_,
        QCOLS, ctab, stab);
}